// round 1
// baseline (speedup 1.0000x reference)
#include <cuda_runtime.h>
#include <math.h>

// Problem constants
#define Bc 4
#define Nc 2048
#define Dc 256
#define Hc 4
#define DHc 64
#define D2c 32
#define Mc (Bc * Nc)          // 8192 rows
#define EPSc 1e-8f

// Scratch (device globals; no allocation allowed)
__device__ float buf_h[Mc * Dc];            // zcRMSNorm output
__device__ float buf_qkv[Mc * 3 * Dc];      // qkv GEMM output
__device__ float buf_q[Bc * Hc * Nc * DHc]; // [bh][n][dh]
__device__ float buf_kT[Bc * Hc * DHc * Nc];// [bh][dh][n]  (transposed!)
__device__ float buf_v[Bc * Hc * Nc * DHc]; // [bh][n][dh]
__device__ float buf_y[Mc * Dc];            // attention out, [b][n][d]
__device__ float buf_yo[Mc * Dc];           // out-proj
__device__ float buf_gt[Mc * Dc];           // gate pre-activation

// ---------------------------------------------------------------------------
// 1) zero-centered RMSNorm: h = (x - mean) / sqrt(mean((x-mean)^2) + eps) * g
// one block (256 threads) per row
// ---------------------------------------------------------------------------
__global__ void rmsnorm_kernel(const float* __restrict__ x,
                               const float* __restrict__ g) {
    int row = blockIdx.x;
    int t = threadIdx.x;
    float v = x[row * Dc + t];
    __shared__ float red[8];
    float s = v;
    #pragma unroll
    for (int o = 16; o; o >>= 1) s += __shfl_xor_sync(0xffffffffu, s, o);
    if ((t & 31) == 0) red[t >> 5] = s;
    __syncthreads();
    float tot = 0.f;
    #pragma unroll
    for (int i = 0; i < 8; i++) tot += red[i];
    float mean = tot * (1.f / Dc);
    float x0 = v - mean;
    float s2 = x0 * x0;
    #pragma unroll
    for (int o = 16; o; o >>= 1) s2 += __shfl_xor_sync(0xffffffffu, s2, o);
    __syncthreads();
    if ((t & 31) == 0) red[t >> 5] = s2;
    __syncthreads();
    float tot2 = 0.f;
    #pragma unroll
    for (int i = 0; i < 8; i++) tot2 += red[i];
    float rinv = rsqrtf(tot2 * (1.f / Dc) + EPSc);
    buf_h[row * Dc + t] = x0 * rinv * g[t];
}

// ---------------------------------------------------------------------------
// 2) SGEMM: C[M,NOUT] = A[M,256] @ W[256,NOUT] + bias
// 64x64 tile per block, BK=16, 256 threads, 4x4 per thread
// ---------------------------------------------------------------------------
template <int NOUT>
__device__ __forceinline__ void sgemm_body(const float* __restrict__ A,
                                           const float* __restrict__ W,
                                           const float* __restrict__ bias,
                                           float* __restrict__ C) {
    __shared__ __align__(16) float As[16][68];  // [k][m]
    __shared__ __align__(16) float Bs[16][68];  // [k][n]
    int tid = threadIdx.x;
    int tx = tid & 15, ty = tid >> 4;
    int rowBase = blockIdx.y * 64;
    int colBase = blockIdx.x * 64;
    float acc[4][4] = {};
    int arow = tid >> 2;             // 0..63
    int ak4 = (tid & 3) * 4;         // 0,4,8,12
    int bkk = tid >> 4;              // 0..15
    int bc4 = (tid & 15) * 4;        // 0..60
    for (int k0 = 0; k0 < Dc; k0 += 16) {
        float4 av = *reinterpret_cast<const float4*>(
            &A[(rowBase + arow) * Dc + k0 + ak4]);
        As[ak4 + 0][arow] = av.x;
        As[ak4 + 1][arow] = av.y;
        As[ak4 + 2][arow] = av.z;
        As[ak4 + 3][arow] = av.w;
        *reinterpret_cast<float4*>(&Bs[bkk][bc4]) =
            *reinterpret_cast<const float4*>(&W[(k0 + bkk) * NOUT + colBase + bc4]);
        __syncthreads();
        #pragma unroll
        for (int k = 0; k < 16; k++) {
            float4 a4 = *reinterpret_cast<const float4*>(&As[k][ty * 4]);
            float4 b4 = *reinterpret_cast<const float4*>(&Bs[k][tx * 4]);
            float a[4] = {a4.x, a4.y, a4.z, a4.w};
            float b[4] = {b4.x, b4.y, b4.z, b4.w};
            #pragma unroll
            for (int i = 0; i < 4; i++)
                #pragma unroll
                for (int j = 0; j < 4; j++)
                    acc[i][j] = fmaf(a[i], b[j], acc[i][j]);
        }
        __syncthreads();
    }
    #pragma unroll
    for (int i = 0; i < 4; i++) {
        int r = rowBase + ty * 4 + i;
        int c = colBase + tx * 4;
        float4 o;
        o.x = acc[i][0] + bias[c + 0];
        o.y = acc[i][1] + bias[c + 1];
        o.z = acc[i][2] + bias[c + 2];
        o.w = acc[i][3] + bias[c + 3];
        *reinterpret_cast<float4*>(&C[r * NOUT + c]) = o;
    }
}

__global__ void gemm_qkv_kernel(const float* __restrict__ W,
                                const float* __restrict__ bias) {
    sgemm_body<3 * Dc>(buf_h, W, bias, buf_qkv);
}
__global__ void gemm_out_kernel(const float* __restrict__ W,
                                const float* __restrict__ bias) {
    sgemm_body<Dc>(buf_y, W, bias, buf_yo);
}
__global__ void gemm_gate_kernel(const float* __restrict__ W,
                                 const float* __restrict__ bias) {
    sgemm_body<Dc>(buf_h, W, bias, buf_gt);
}

// ---------------------------------------------------------------------------
// 3) RoPE + scatter qkv -> q [bh][n][dh], kT [bh][dh][n], v [bh][n][dh]
// one thread per (m, head, freq-pair)
// ---------------------------------------------------------------------------
__global__ void rope_kernel(const float* __restrict__ freqs) {
    int gid = blockIdx.x * blockDim.x + threadIdx.x;   // < M*H*D2 = 1048576
    int m = gid >> 7;          // / (H*D2) = 128
    int rest = gid & 127;
    int h = rest >> 5;
    int i = rest & 31;
    int n = m & (Nc - 1);
    int b = m >> 11;
    float c = freqs[n * (D2c * 2) + i * 2 + 0];
    float s = freqs[n * (D2c * 2) + i * 2 + 1];
    const float* base = &buf_qkv[m * (3 * Dc)];
    int off = h * DHc + 2 * i;
    float q0 = base[0 * Dc + off], q1 = base[0 * Dc + off + 1];
    float k0 = base[1 * Dc + off], k1 = base[1 * Dc + off + 1];
    float v0 = base[2 * Dc + off], v1 = base[2 * Dc + off + 1];
    float qe = q0 * c - q1 * s, qo = q0 * s + q1 * c;
    float ke = k0 * c - k1 * s, ko = k0 * s + k1 * c;
    int bh = b * Hc + h;
    int qbase = bh * Nc * DHc + n * DHc + 2 * i;
    buf_q[qbase + 0] = qe;
    buf_q[qbase + 1] = qo;
    buf_kT[bh * DHc * Nc + (2 * i + 0) * Nc + n] = ke;
    buf_kT[bh * DHc * Nc + (2 * i + 1) * Nc + n] = ko;
    buf_v[qbase + 0] = v0;
    buf_v[qbase + 1] = v1;
}

// ---------------------------------------------------------------------------
// 4) Flash attention, fp32. 16 q rows per block, K/V tiles of 64 in SMEM.
// 256 threads: thread (r = tid/16, i = tid%16) owns score cols 4i..4i+3 and
// output dims 4i..4i+3 of q-row r. Online softmax over 32 tiles.
// ---------------------------------------------------------------------------
__global__ void attn_kernel() {
    __shared__ __align__(16) float kt_s[DHc][68];  // [d][c]
    __shared__ __align__(16) float vt_s[64][68];   // [c][d]
    __shared__ __align__(16) float qs[16][64];     // [r][d]
    __shared__ __align__(16) float sp[16][68];     // [r][c] probabilities

    int tid = threadIdx.x;
    int bh = blockIdx.x >> 7;     // 0..15
    int qt = blockIdx.x & 127;
    int qBase = qt * 16;
    int b = bh >> 2, h = bh & 3;
    const float* Q = buf_q + bh * Nc * DHc;
    const float* KT = buf_kT + bh * DHc * Nc;
    const float* V = buf_v + bh * Nc * DHc;

    {   // load 16x64 q tile (coalesced float4)
        int r = tid >> 4, d4 = (tid & 15) * 4;
        *reinterpret_cast<float4*>(&qs[r][d4]) =
            *reinterpret_cast<const float4*>(&Q[(qBase + r) * DHc + d4]);
    }

    int r = tid >> 4;
    int cb = (tid & 15) * 4;
    float mrow = -INFINITY, lrow = 0.f;
    float ax = 0.f, ay = 0.f, az = 0.f, aw = 0.f;

    for (int kb = 0; kb < Nc; kb += 64) {
        __syncthreads();  // protects kt/vt/sp reuse; covers qs on first iter
        #pragma unroll
        for (int j = 0; j < 4; j++) {
            int idx = tid + j * 256;           // 0..1023
            int a0 = idx >> 4;                 // 0..63
            int a4 = (idx & 15) * 4;           // 0..60
            *reinterpret_cast<float4*>(&kt_s[a0][a4]) =
                *reinterpret_cast<const float4*>(&KT[a0 * Nc + kb + a4]);
            *reinterpret_cast<float4*>(&vt_s[a0][a4]) =
                *reinterpret_cast<const float4*>(&V[(kb + a0) * DHc + a4]);
        }
        __syncthreads();

        // scores: s[r][cb..cb+3] = q[r] . K[cb..cb+3]
        float s0 = 0.f, s1 = 0.f, s2 = 0.f, s3 = 0.f;
        #pragma unroll 16
        for (int d = 0; d < DHc; d++) {
            float qv = qs[r][d];
            float4 k4 = *reinterpret_cast<const float4*>(&kt_s[d][cb]);
            s0 = fmaf(qv, k4.x, s0);
            s1 = fmaf(qv, k4.y, s1);
            s2 = fmaf(qv, k4.z, s2);
            s3 = fmaf(qv, k4.w, s3);
        }
        s0 *= 0.125f; s1 *= 0.125f; s2 *= 0.125f; s3 *= 0.125f;

        // online softmax update (16-lane row team, within one warp)
        float tmax = fmaxf(fmaxf(s0, s1), fmaxf(s2, s3));
        #pragma unroll
        for (int o = 8; o; o >>= 1)
            tmax = fmaxf(tmax, __shfl_xor_sync(0xffffffffu, tmax, o));
        float newm = fmaxf(mrow, tmax);
        float f = __expf(mrow - newm);   // 0 on first tile (mrow = -inf)
        float p0 = __expf(s0 - newm), p1 = __expf(s1 - newm);
        float p2 = __expf(s2 - newm), p3 = __expf(s3 - newm);
        float psum = p0 + p1 + p2 + p3;
        #pragma unroll
        for (int o = 8; o; o >>= 1)
            psum += __shfl_xor_sync(0xffffffffu, psum, o);
        lrow = lrow * f + psum;
        ax *= f; ay *= f; az *= f; aw *= f;
        mrow = newm;

        *reinterpret_cast<float4*>(&sp[r][cb]) = make_float4(p0, p1, p2, p3);
        __syncwarp();

        // accumulate y[r][cb..cb+3] += sum_c p[r][c] * V[c][cb..cb+3]
        #pragma unroll 16
        for (int c = 0; c < 64; c++) {
            float p = sp[r][c];
            float4 v4 = *reinterpret_cast<const float4*>(&vt_s[c][cb]);
            ax = fmaf(p, v4.x, ax);
            ay = fmaf(p, v4.y, ay);
            az = fmaf(p, v4.z, az);
            aw = fmaf(p, v4.w, aw);
        }
    }

    float inv = 1.f / lrow;
    int n = qBase + r;
    float4 o = make_float4(ax * inv, ay * inv, az * inv, aw * inv);
    *reinterpret_cast<float4*>(&buf_y[(b * Nc + n) * Dc + h * DHc + cb]) = o;
}

// ---------------------------------------------------------------------------
// 5) out = x + sigmoid(gate_pre) * y_out
// ---------------------------------------------------------------------------
__global__ void final_kernel(const float* __restrict__ x,
                             float* __restrict__ out) {
    int i = blockIdx.x * blockDim.x + threadIdx.x;
    float z = buf_gt[i];
    float gate = 1.f / (1.f + __expf(-z));
    out[i] = x[i] + gate * buf_yo[i];
}

// ---------------------------------------------------------------------------
extern "C" void kernel_launch(void* const* d_in, const int* in_sizes, int n_in,
                              void* d_out, int out_size) {
    (void)in_sizes; (void)n_in; (void)out_size;
    const float* x      = (const float*)d_in[0];
    const float* freqs  = (const float*)d_in[1];
    const float* g      = (const float*)d_in[2];
    const float* w_qkv  = (const float*)d_in[3];
    const float* b_qkv  = (const float*)d_in[4];
    const float* w_out  = (const float*)d_in[5];
    const float* b_out  = (const float*)d_in[6];
    const float* w_gate = (const float*)d_in[7];
    const float* b_gate = (const float*)d_in[8];
    float* out = (float*)d_out;

    rmsnorm_kernel<<<Mc, Dc>>>(x, g);
    gemm_qkv_kernel<<<dim3(12, 128), 256>>>(w_qkv, b_qkv);
    rope_kernel<<<(Mc * Hc * D2c) / 256, 256>>>(freqs);
    attn_kernel<<<Bc * Hc * (Nc / 16), 256>>>();
    gemm_out_kernel<<<dim3(4, 128), 256>>>(w_out, b_out);
    gemm_gate_kernel<<<dim3(4, 128), 256>>>(w_gate, b_gate);
    final_kernel<<<(Mc * Dc) / 256, 256>>>(x, out);
}

// round 2
// speedup vs baseline: 4.4391x; 4.4391x over previous
#include <cuda_runtime.h>
#include <math.h>

// Problem constants
#define Bc 4
#define Nc 2048
#define Dc 256
#define Hc 4
#define DHc 64
#define D2c 32
#define Mc (Bc * Nc)          // 8192 rows
#define EPSc 1e-8f
#define LD 72                 // smem row stride (mod 32 == 8)

// Scratch (device globals; no allocation allowed)
__device__ float buf_h[Mc * Dc];
__device__ float buf_qkv[Mc * 3 * Dc];
__device__ float buf_q[Bc * Hc * Nc * DHc]; // [bh][n][dh]
__device__ float buf_k[Bc * Hc * Nc * DHc]; // [bh][n][dh]
__device__ float buf_v[Bc * Hc * Nc * DHc]; // [bh][n][dh]
__device__ float buf_y[Mc * Dc];
__device__ float buf_yo[Mc * Dc];
__device__ float buf_gt[Mc * Dc];

// ---------------------------------------------------------------------------
// tf32 helpers
// ---------------------------------------------------------------------------
__device__ __forceinline__ unsigned f2tf(float f) {
    unsigned u;
    asm("cvt.rna.tf32.f32 %0, %1;" : "=r"(u) : "f"(f));
    return u;
}
__device__ __forceinline__ void mma8(float4& d, unsigned a0, unsigned a1,
                                     unsigned a2, unsigned a3,
                                     unsigned b0, unsigned b1) {
    asm volatile(
        "mma.sync.aligned.m16n8k8.row.col.f32.tf32.tf32.f32 "
        "{%0,%1,%2,%3},{%4,%5,%6,%7},{%8,%9},{%0,%1,%2,%3};"
        : "+f"(d.x), "+f"(d.y), "+f"(d.z), "+f"(d.w)
        : "r"(a0), "r"(a1), "r"(a2), "r"(a3), "r"(b0), "r"(b1));
}
// swizzled smem index: xor col bit2 with row bit2 -> conflict-free B frags
__device__ __forceinline__ int swz(int r, int c) {
    return r * LD + (c ^ (((r >> 2) & 1) << 2));
}

// ---------------------------------------------------------------------------
// 1) zero-centered RMSNorm
// ---------------------------------------------------------------------------
__global__ void rmsnorm_kernel(const float* __restrict__ x,
                               const float* __restrict__ g) {
    int row = blockIdx.x;
    int t = threadIdx.x;
    float v = x[row * Dc + t];
    __shared__ float red[8];
    float s = v;
    #pragma unroll
    for (int o = 16; o; o >>= 1) s += __shfl_xor_sync(0xffffffffu, s, o);
    if ((t & 31) == 0) red[t >> 5] = s;
    __syncthreads();
    float tot = 0.f;
    #pragma unroll
    for (int i = 0; i < 8; i++) tot += red[i];
    float mean = tot * (1.f / Dc);
    float x0 = v - mean;
    float s2 = x0 * x0;
    #pragma unroll
    for (int o = 16; o; o >>= 1) s2 += __shfl_xor_sync(0xffffffffu, s2, o);
    __syncthreads();
    if ((t & 31) == 0) red[t >> 5] = s2;
    __syncthreads();
    float tot2 = 0.f;
    #pragma unroll
    for (int i = 0; i < 8; i++) tot2 += red[i];
    float rinv = rsqrtf(tot2 * (1.f / Dc) + EPSc);
    buf_h[row * Dc + t] = x0 * rinv * g[t];
}

// ---------------------------------------------------------------------------
// 2) tf32 mma GEMM: C[M,NOUT] = A[M,256] @ W[256,NOUT] + bias
// 64x64 tile per block, 128 threads (4 warps x 16 rows), k-chunks of 64
// ---------------------------------------------------------------------------
template <int NOUT>
__device__ __forceinline__ void mma_gemm(const float* __restrict__ A,
                                         const float* __restrict__ W,
                                         const float* __restrict__ bias,
                                         float* __restrict__ C) {
    __shared__ unsigned As[64 * LD];
    __shared__ unsigned Ws[64 * LD];
    int tid = threadIdx.x;
    int wid = tid >> 5, lane = tid & 31;
    int gid = lane >> 2, tig = lane & 3;
    int rowBase = blockIdx.y * 64;
    int colBase = blockIdx.x * 64;
    int wr = wid * 16;
    float4 acc[8];
    #pragma unroll
    for (int i = 0; i < 8; i++) acc[i] = make_float4(0.f, 0.f, 0.f, 0.f);

    for (int k0 = 0; k0 < Dc; k0 += 64) {
        __syncthreads();
        #pragma unroll
        for (int j = 0; j < 8; j++) {
            int fid = tid + 128 * j;
            int r = fid >> 4, c = (fid & 15) * 4;
            float4 av = *reinterpret_cast<const float4*>(
                &A[(rowBase + r) * Dc + k0 + c]);
            *reinterpret_cast<uint4*>(&As[swz(r, c)]) =
                make_uint4(f2tf(av.x), f2tf(av.y), f2tf(av.z), f2tf(av.w));
            float4 wv = *reinterpret_cast<const float4*>(
                &W[(k0 + r) * NOUT + colBase + c]);
            *reinterpret_cast<uint4*>(&Ws[swz(r, c)]) =
                make_uint4(f2tf(wv.x), f2tf(wv.y), f2tf(wv.z), f2tf(wv.w));
        }
        __syncthreads();
        #pragma unroll
        for (int ks = 0; ks < 8; ks++) {
            unsigned a0 = As[swz(wr + gid, ks * 8 + tig)];
            unsigned a1 = As[swz(wr + gid + 8, ks * 8 + tig)];
            unsigned a2 = As[swz(wr + gid, ks * 8 + tig + 4)];
            unsigned a3 = As[swz(wr + gid + 8, ks * 8 + tig + 4)];
            #pragma unroll
            for (int nt = 0; nt < 8; nt++) {
                unsigned b0 = Ws[swz(ks * 8 + tig, nt * 8 + gid)];
                unsigned b1 = Ws[swz(ks * 8 + tig + 4, nt * 8 + gid)];
                mma8(acc[nt], a0, a1, a2, a3, b0, b1);
            }
        }
    }
    #pragma unroll
    for (int nt = 0; nt < 8; nt++) {
        int col = colBase + nt * 8 + tig * 2;
        int r0 = rowBase + wr + gid, r1 = r0 + 8;
        *reinterpret_cast<float2*>(&C[r0 * NOUT + col]) =
            make_float2(acc[nt].x + bias[col], acc[nt].y + bias[col + 1]);
        *reinterpret_cast<float2*>(&C[r1 * NOUT + col]) =
            make_float2(acc[nt].z + bias[col], acc[nt].w + bias[col + 1]);
    }
}

__global__ __launch_bounds__(128) void gemm_qkv_kernel(
    const float* __restrict__ W, const float* __restrict__ bias) {
    mma_gemm<3 * Dc>(buf_h, W, bias, buf_qkv);
}
__global__ __launch_bounds__(128) void gemm_out_kernel(
    const float* __restrict__ W, const float* __restrict__ bias) {
    mma_gemm<Dc>(buf_y, W, bias, buf_yo);
}
__global__ __launch_bounds__(128) void gemm_gate_kernel(
    const float* __restrict__ W, const float* __restrict__ bias) {
    mma_gemm<Dc>(buf_h, W, bias, buf_gt);
}

// ---------------------------------------------------------------------------
// 3) RoPE + scatter qkv -> q/k/v in [bh][n][dh]
// ---------------------------------------------------------------------------
__global__ void rope_kernel(const float* __restrict__ freqs) {
    int gid = blockIdx.x * blockDim.x + threadIdx.x;
    int m = gid >> 7;
    int rest = gid & 127;
    int h = rest >> 5;
    int i = rest & 31;
    int n = m & (Nc - 1);
    int b = m >> 11;
    float c = freqs[n * (D2c * 2) + i * 2 + 0];
    float s = freqs[n * (D2c * 2) + i * 2 + 1];
    const float* base = &buf_qkv[m * (3 * Dc)];
    int off = h * DHc + 2 * i;
    float q0 = base[0 * Dc + off], q1 = base[0 * Dc + off + 1];
    float k0 = base[1 * Dc + off], k1 = base[1 * Dc + off + 1];
    float v0 = base[2 * Dc + off], v1 = base[2 * Dc + off + 1];
    float qe = q0 * c - q1 * s, qo = q0 * s + q1 * c;
    float ke = k0 * c - k1 * s, ko = k0 * s + k1 * c;
    int bh = b * Hc + h;
    int qbase = bh * Nc * DHc + n * DHc + 2 * i;
    buf_q[qbase + 0] = qe;
    buf_q[qbase + 1] = qo;
    buf_k[qbase + 0] = ke;
    buf_k[qbase + 1] = ko;
    buf_v[qbase + 0] = v0;
    buf_v[qbase + 1] = v1;
}

// ---------------------------------------------------------------------------
// 4) Flash attention with tf32 mma. 64 q-rows/block, 4 warps x 16 rows.
// Q fragments in registers; K/V 64-wide tiles in smem (tf32 bits);
// P re-fragmented through the K smem region (free after the QK phase).
// ---------------------------------------------------------------------------
__global__ __launch_bounds__(128) void attn_mma_kernel() {
    __shared__ unsigned Ks[64 * LD];
    __shared__ unsigned Vs[64 * LD];

    int tid = threadIdx.x;
    int wid = tid >> 5, lane = tid & 31;
    int gid = lane >> 2, tig = lane & 3;
    int bh = blockIdx.x >> 5;     // 16 heads*batch
    int qt = blockIdx.x & 31;     // 32 q tiles of 64
    int qBase = qt * 64;
    int b = bh >> 2, h = bh & 3;
    const float* Q = buf_q + bh * Nc * DHc;
    const float* K = buf_k + bh * Nc * DHc;
    const float* V = buf_v + bh * Nc * DHc;
    int wr = wid * 16;

    // Q fragments (16 x 64 per warp) in registers
    unsigned qa[8][4];
    {
        const float* qp = Q + (qBase + wr) * DHc;
        #pragma unroll
        for (int ks = 0; ks < 8; ks++) {
            int c = ks * 8 + tig;
            qa[ks][0] = f2tf(qp[gid * DHc + c]);
            qa[ks][1] = f2tf(qp[(gid + 8) * DHc + c]);
            qa[ks][2] = f2tf(qp[gid * DHc + c + 4]);
            qa[ks][3] = f2tf(qp[(gid + 8) * DHc + c + 4]);
        }
    }

    float4 oacc[8];
    #pragma unroll
    for (int i = 0; i < 8; i++) oacc[i] = make_float4(0.f, 0.f, 0.f, 0.f);
    float m0 = -1e30f, m1 = -1e30f, l0 = 0.f, l1 = 0.f;

    for (int kb = 0; kb < Nc; kb += 64) {
        __syncthreads();   // previous tile's P/V reads done
        #pragma unroll
        for (int j = 0; j < 8; j++) {
            int fid = tid + 128 * j;
            int r = fid >> 4, c = (fid & 15) * 4;
            float4 kv = *reinterpret_cast<const float4*>(&K[(kb + r) * DHc + c]);
            float4 vv = *reinterpret_cast<const float4*>(&V[(kb + r) * DHc + c]);
            *reinterpret_cast<uint4*>(&Ks[swz(r, c)]) =
                make_uint4(f2tf(kv.x), f2tf(kv.y), f2tf(kv.z), f2tf(kv.w));
            *reinterpret_cast<uint4*>(&Vs[swz(r, c)]) =
                make_uint4(f2tf(vv.x), f2tf(vv.y), f2tf(vv.z), f2tf(vv.w));
        }
        __syncthreads();

        // S = Q K^T  (16x64 per warp)
        float4 s[8];
        #pragma unroll
        for (int nt = 0; nt < 8; nt++) {
            float4 acc = make_float4(0.f, 0.f, 0.f, 0.f);
            #pragma unroll
            for (int ks = 0; ks < 8; ks++) {
                unsigned b0 = Ks[swz(nt * 8 + gid, ks * 8 + tig)];
                unsigned b1 = Ks[swz(nt * 8 + gid, ks * 8 + tig + 4)];
                mma8(acc, qa[ks][0], qa[ks][1], qa[ks][2], qa[ks][3], b0, b1);
            }
            s[nt] = acc;
        }

        // online softmax (rows gid and gid+8; row team = quad)
        float tm0 = -1e30f, tm1 = -1e30f;
        #pragma unroll
        for (int nt = 0; nt < 8; nt++) {
            s[nt].x *= 0.125f; s[nt].y *= 0.125f;
            s[nt].z *= 0.125f; s[nt].w *= 0.125f;
            tm0 = fmaxf(tm0, fmaxf(s[nt].x, s[nt].y));
            tm1 = fmaxf(tm1, fmaxf(s[nt].z, s[nt].w));
        }
        tm0 = fmaxf(tm0, __shfl_xor_sync(0xffffffffu, tm0, 1));
        tm0 = fmaxf(tm0, __shfl_xor_sync(0xffffffffu, tm0, 2));
        tm1 = fmaxf(tm1, __shfl_xor_sync(0xffffffffu, tm1, 1));
        tm1 = fmaxf(tm1, __shfl_xor_sync(0xffffffffu, tm1, 2));
        float nm0 = fmaxf(m0, tm0), nm1 = fmaxf(m1, tm1);
        float f0 = __expf(m0 - nm0), f1 = __expf(m1 - nm1);
        m0 = nm0; m1 = nm1;
        float ps0 = 0.f, ps1 = 0.f;
        #pragma unroll
        for (int nt = 0; nt < 8; nt++) {
            s[nt].x = __expf(s[nt].x - nm0);
            s[nt].y = __expf(s[nt].y - nm0);
            s[nt].z = __expf(s[nt].z - nm1);
            s[nt].w = __expf(s[nt].w - nm1);
            ps0 += s[nt].x + s[nt].y;
            ps1 += s[nt].z + s[nt].w;
        }
        ps0 += __shfl_xor_sync(0xffffffffu, ps0, 1);
        ps0 += __shfl_xor_sync(0xffffffffu, ps0, 2);
        ps1 += __shfl_xor_sync(0xffffffffu, ps1, 1);
        ps1 += __shfl_xor_sync(0xffffffffu, ps1, 2);
        l0 = l0 * f0 + ps0;
        l1 = l1 * f1 + ps1;
        #pragma unroll
        for (int nt = 0; nt < 8; nt++) {
            oacc[nt].x *= f0; oacc[nt].y *= f0;
            oacc[nt].z *= f1; oacc[nt].w *= f1;
        }

        __syncthreads();   // all warps done reading Ks
        // store P into Ks rows [wr, wr+16) as tf32 A-fragments source
        #pragma unroll
        for (int nt = 0; nt < 8; nt++) {
            int c = nt * 8 + tig * 2;
            Ks[swz(wr + gid, c)]     = f2tf(s[nt].x);
            Ks[swz(wr + gid, c + 1)] = f2tf(s[nt].y);
            Ks[swz(wr + gid + 8, c)]     = f2tf(s[nt].z);
            Ks[swz(wr + gid + 8, c + 1)] = f2tf(s[nt].w);
        }
        __syncwarp();

        // O += P V  (16x64 per warp)
        #pragma unroll
        for (int ks = 0; ks < 8; ks++) {
            unsigned a0 = Ks[swz(wr + gid, ks * 8 + tig)];
            unsigned a1 = Ks[swz(wr + gid + 8, ks * 8 + tig)];
            unsigned a2 = Ks[swz(wr + gid, ks * 8 + tig + 4)];
            unsigned a3 = Ks[swz(wr + gid + 8, ks * 8 + tig + 4)];
            #pragma unroll
            for (int nt = 0; nt < 8; nt++) {
                unsigned b0 = Vs[swz(ks * 8 + tig, nt * 8 + gid)];
                unsigned b1 = Vs[swz(ks * 8 + tig + 4, nt * 8 + gid)];
                mma8(oacc[nt], a0, a1, a2, a3, b0, b1);
            }
        }
    }

    float i0 = 1.f / l0, i1 = 1.f / l1;
    #pragma unroll
    for (int nt = 0; nt < 8; nt++) {
        int col = h * DHc + nt * 8 + tig * 2;
        int r0 = b * Nc + qBase + wr + gid;
        int r1 = r0 + 8;
        *reinterpret_cast<float2*>(&buf_y[r0 * Dc + col]) =
            make_float2(oacc[nt].x * i0, oacc[nt].y * i0);
        *reinterpret_cast<float2*>(&buf_y[r1 * Dc + col]) =
            make_float2(oacc[nt].z * i1, oacc[nt].w * i1);
    }
}

// ---------------------------------------------------------------------------
// 5) out = x + sigmoid(gate_pre) * y_out
// ---------------------------------------------------------------------------
__global__ void final_kernel(const float* __restrict__ x,
                             float* __restrict__ out) {
    int i = blockIdx.x * blockDim.x + threadIdx.x;
    float z = buf_gt[i];
    float gate = 1.f / (1.f + __expf(-z));
    out[i] = x[i] + gate * buf_yo[i];
}

// ---------------------------------------------------------------------------
extern "C" void kernel_launch(void* const* d_in, const int* in_sizes, int n_in,
                              void* d_out, int out_size) {
    (void)in_sizes; (void)n_in; (void)out_size;
    const float* x      = (const float*)d_in[0];
    const float* freqs  = (const float*)d_in[1];
    const float* g      = (const float*)d_in[2];
    const float* w_qkv  = (const float*)d_in[3];
    const float* b_qkv  = (const float*)d_in[4];
    const float* w_out  = (const float*)d_in[5];
    const float* b_out  = (const float*)d_in[6];
    const float* w_gate = (const float*)d_in[7];
    const float* b_gate = (const float*)d_in[8];
    float* out = (float*)d_out;

    rmsnorm_kernel<<<Mc, Dc>>>(x, g);
    gemm_qkv_kernel<<<dim3(12, 128), 128>>>(w_qkv, b_qkv);
    rope_kernel<<<(Mc * Hc * D2c) / 256, 256>>>(freqs);
    attn_mma_kernel<<<Bc * Hc * (Nc / 64), 128>>>();
    gemm_out_kernel<<<dim3(4, 128), 128>>>(w_out, b_out);
    gemm_gate_kernel<<<dim3(4, 128), 128>>>(w_gate, b_gate);
    final_kernel<<<(Mc * Dc) / 256, 256>>>(x, out);
}

// round 3
// speedup vs baseline: 9.1653x; 2.0647x over previous
#include <cuda_runtime.h>
#include <cuda_bf16.h>
#include <math.h>

// Problem constants
#define Bc 4
#define Nc 2048
#define Dc 256
#define Hc 4
#define DHc 64
#define Mc (Bc * Nc)          // 8192 rows
#define EPSc 1e-8f
#define LDH 72                // smem row pitch in halves (144B: ldsm conflict-free)

// Scratch (device globals; no allocation allowed)
__device__ __nv_bfloat16 buf_hb[Mc * Dc];          // normalized h, bf16
__device__ __nv_bfloat16 buf_q[Bc * Hc * Nc * DHc];
__device__ __nv_bfloat16 buf_k[Bc * Hc * Nc * DHc];
__device__ __nv_bfloat16 buf_v[Bc * Hc * Nc * DHc];
__device__ __nv_bfloat16 buf_yb[Mc * Dc];          // attention out, bf16
__device__ float buf_yo[Mc * Dc];
__device__ float buf_gt[Mc * Dc];

// ---------------------------------------------------------------------------
// helpers
// ---------------------------------------------------------------------------
__device__ __forceinline__ unsigned pack_bf(float x, float y) {
    __nv_bfloat162 h = __float22bfloat162_rn(make_float2(x, y));
    return *reinterpret_cast<unsigned*>(&h);
}
__device__ __forceinline__ void mma16(float4& d, unsigned a0, unsigned a1,
                                      unsigned a2, unsigned a3,
                                      unsigned b0, unsigned b1) {
    asm volatile(
        "mma.sync.aligned.m16n8k16.row.col.f32.bf16.bf16.f32 "
        "{%0,%1,%2,%3},{%4,%5,%6,%7},{%8,%9},{%0,%1,%2,%3};"
        : "+f"(d.x), "+f"(d.y), "+f"(d.z), "+f"(d.w)
        : "r"(a0), "r"(a1), "r"(a2), "r"(a3), "r"(b0), "r"(b1));
}
__device__ __forceinline__ void ldsm4(unsigned& r0, unsigned& r1, unsigned& r2,
                                      unsigned& r3, const void* p) {
    unsigned a = (unsigned)__cvta_generic_to_shared(p);
    asm volatile("ldmatrix.sync.aligned.m8n8.x4.shared.b16 {%0,%1,%2,%3},[%4];"
                 : "=r"(r0), "=r"(r1), "=r"(r2), "=r"(r3) : "r"(a));
}
__device__ __forceinline__ void ldsm4t(unsigned& r0, unsigned& r1, unsigned& r2,
                                       unsigned& r3, const void* p) {
    unsigned a = (unsigned)__cvta_generic_to_shared(p);
    asm volatile("ldmatrix.sync.aligned.m8n8.x4.trans.shared.b16 {%0,%1,%2,%3},[%4];"
                 : "=r"(r0), "=r"(r1), "=r"(r2), "=r"(r3) : "r"(a));
}

// ---------------------------------------------------------------------------
// 1) zero-centered RMSNorm -> bf16 h
// ---------------------------------------------------------------------------
__global__ void rmsnorm_kernel(const float* __restrict__ x,
                               const float* __restrict__ g) {
    int row = blockIdx.x;
    int t = threadIdx.x;
    float v = x[row * Dc + t];
    __shared__ float red[8];
    float s = v;
    #pragma unroll
    for (int o = 16; o; o >>= 1) s += __shfl_xor_sync(0xffffffffu, s, o);
    if ((t & 31) == 0) red[t >> 5] = s;
    __syncthreads();
    float tot = 0.f;
    #pragma unroll
    for (int i = 0; i < 8; i++) tot += red[i];
    float mean = tot * (1.f / Dc);
    float x0 = v - mean;
    float s2 = x0 * x0;
    #pragma unroll
    for (int o = 16; o; o >>= 1) s2 += __shfl_xor_sync(0xffffffffu, s2, o);
    __syncthreads();
    if ((t & 31) == 0) red[t >> 5] = s2;
    __syncthreads();
    float tot2 = 0.f;
    #pragma unroll
    for (int i = 0; i < 8; i++) tot2 += red[i];
    float rinv = rsqrtf(tot2 * (1.f / Dc) + EPSc);
    buf_hb[row * Dc + t] = __float2bfloat16(x0 * rinv * g[t]);
}

// ---------------------------------------------------------------------------
// 2) bf16 mma GEMM mainloop: acc[8] = A[64 rows, 256] @ W[256, 64 cols]
//    A is bf16 row-major, W is fp32 row-major (converted on load).
//    128 threads (4 warps x 16 rows).
// ---------------------------------------------------------------------------
template <int NOUT>
__device__ __forceinline__ void gemm_main(const __nv_bfloat16* __restrict__ A,
                                          const float* __restrict__ W,
                                          float4 acc[8], int rowBase, int colBase) {
    __shared__ __align__(16) __nv_bfloat16 As[64][LDH];
    __shared__ __align__(16) __nv_bfloat16 Ws[64][LDH];
    int tid = threadIdx.x;
    int wid = tid >> 5, lane = tid & 31;
    int wr = wid * 16;
    #pragma unroll
    for (int i = 0; i < 8; i++) acc[i] = make_float4(0.f, 0.f, 0.f, 0.f);

    for (int k0 = 0; k0 < Dc; k0 += 64) {
        __syncthreads();
        #pragma unroll
        for (int j = 0; j < 4; j++) {      // A: 512 x 8-half chunks
            int fid = tid + 128 * j;
            int r = fid >> 3, c8 = (fid & 7) * 8;
            *reinterpret_cast<uint4*>(&As[r][c8]) =
                *reinterpret_cast<const uint4*>(&A[(rowBase + r) * Dc + k0 + c8]);
        }
        #pragma unroll
        for (int j = 0; j < 8; j++) {      // W: 1024 float4 -> bf16
            int fid = tid + 128 * j;
            int r = fid >> 4, c4 = (fid & 15) * 4;
            float4 wv = *reinterpret_cast<const float4*>(
                &W[(k0 + r) * NOUT + colBase + c4]);
            *reinterpret_cast<uint2*>(&Ws[r][c4]) =
                make_uint2(pack_bf(wv.x, wv.y), pack_bf(wv.z, wv.w));
        }
        __syncthreads();
        #pragma unroll
        for (int ks = 0; ks < 4; ks++) {
            unsigned a0, a1, a2, a3;
            ldsm4(a0, a1, a2, a3, &As[wr + (lane & 15)][ks * 16 + (lane >> 4) * 8]);
            #pragma unroll
            for (int p = 0; p < 4; p++) {
                unsigned b0, b1, b2, b3;
                ldsm4t(b0, b1, b2, b3,
                       &Ws[ks * 16 + (lane & 7) + 8 * ((lane >> 3) & 1)]
                          [p * 16 + (lane >> 4) * 8]);
                mma16(acc[2 * p], a0, a1, a2, a3, b0, b1);
                mma16(acc[2 * p + 1], a0, a1, a2, a3, b2, b3);
            }
        }
    }
}

// QKV GEMM with fused bias + RoPE + head scatter (bf16 outputs)
__global__ __launch_bounds__(128) void gemm_qkv_kernel(
    const float* __restrict__ W, const float* __restrict__ bias,
    const float* __restrict__ freqs) {
    int rowBase = blockIdx.y * 64;
    int colBase = blockIdx.x * 64;
    float4 acc[8];
    gemm_main<3 * Dc>(buf_hb, W, acc, rowBase, colBase);

    int tid = threadIdx.x;
    int wid = tid >> 5, lane = tid & 31;
    int gid = lane >> 2, tig = lane & 3;
    int sec = colBase >> 8;  // 0=q 1=k 2=v (uniform per block)
    unsigned* dst = sec == 0 ? reinterpret_cast<unsigned*>(buf_q)
                  : sec == 1 ? reinterpret_cast<unsigned*>(buf_k)
                             : reinterpret_cast<unsigned*>(buf_v);
    int r0 = rowBase + wid * 16 + gid, r1 = r0 + 8;
    int n0 = r0 & (Nc - 1), n1 = r1 & (Nc - 1);
    int b0i = r0 >> 11, b1i = r1 >> 11;
    #pragma unroll
    for (int nt = 0; nt < 8; nt++) {
        int col = colBase + nt * 8 + tig * 2;
        int c = col & 255, h = c >> 6, i = (c & 63) >> 1;
        float bx = bias[col], by = bias[col + 1];
        float v0 = acc[nt].x + bx, v1 = acc[nt].y + by;
        float w0 = acc[nt].z + bx, w1 = acc[nt].w + by;
        if (sec < 2) {
            float2 cs0 = *reinterpret_cast<const float2*>(&freqs[n0 * 64 + i * 2]);
            float2 cs1 = *reinterpret_cast<const float2*>(&freqs[n1 * 64 + i * 2]);
            float t0 = v0 * cs0.x - v1 * cs0.y;
            v1 = v0 * cs0.y + v1 * cs0.x; v0 = t0;
            float t1 = w0 * cs1.x - w1 * cs1.y;
            w1 = w0 * cs1.y + w1 * cs1.x; w0 = t1;
        }
        dst[((b0i * Hc + h) * Nc + n0) * 32 + i] = pack_bf(v0, v1);
        dst[((b1i * Hc + h) * Nc + n1) * 32 + i] = pack_bf(w0, w1);
    }
}

// Fused out-proj (z=0) and gate (z=1) GEMM, fp32 output + bias
__global__ __launch_bounds__(128) void gemm_og_kernel(
    const float* __restrict__ Wo, const float* __restrict__ bo,
    const float* __restrict__ Wg, const float* __restrict__ bg) {
    bool gate = blockIdx.z != 0;
    const __nv_bfloat16* A = gate ? buf_hb : buf_yb;
    const float* W = gate ? Wg : Wo;
    const float* bias = gate ? bg : bo;
    float* C = gate ? buf_gt : buf_yo;
    int rowBase = blockIdx.y * 64;
    int colBase = blockIdx.x * 64;
    float4 acc[8];
    gemm_main<Dc>(A, W, acc, rowBase, colBase);

    int tid = threadIdx.x;
    int wid = tid >> 5, lane = tid & 31;
    int gid = lane >> 2, tig = lane & 3;
    #pragma unroll
    for (int nt = 0; nt < 8; nt++) {
        int col = colBase + nt * 8 + tig * 2;
        int r0 = rowBase + wid * 16 + gid, r1 = r0 + 8;
        *reinterpret_cast<float2*>(&C[r0 * Dc + col]) =
            make_float2(acc[nt].x + bias[col], acc[nt].y + bias[col + 1]);
        *reinterpret_cast<float2*>(&C[r1 * Dc + col]) =
            make_float2(acc[nt].z + bias[col], acc[nt].w + bias[col + 1]);
    }
}

// ---------------------------------------------------------------------------
// 3) Flash attention, bf16 mma m16n8k16 + ldmatrix.
//    64 q-rows/block (4 warps x 16), K/V tiles of 64, online softmax.
// ---------------------------------------------------------------------------
__global__ __launch_bounds__(128) void attn_kernel() {
    __shared__ __align__(16) __nv_bfloat16 Ks[64][LDH];
    __shared__ __align__(16) __nv_bfloat16 Vs[64][LDH];
    __shared__ __align__(16) __nv_bfloat16 Ps[64][LDH];

    int tid = threadIdx.x;
    int wid = tid >> 5, lane = tid & 31;
    int gid = lane >> 2, tig = lane & 3;
    int bh = blockIdx.x >> 5;
    int qt = blockIdx.x & 31;
    int qBase = qt * 64;
    int b = bh >> 2, h = bh & 3;
    const __nv_bfloat16* Q = buf_q + bh * Nc * DHc;
    const __nv_bfloat16* K = buf_k + bh * Nc * DHc;
    const __nv_bfloat16* V = buf_v + bh * Nc * DHc;
    int wr = wid * 16;

    // Q A-fragments straight from global (pairs are 32-bit words)
    unsigned qa[4][4];
    {
        const __nv_bfloat16* qp = Q + (qBase + wr) * DHc;
        #pragma unroll
        for (int ks = 0; ks < 4; ks++) {
            int c = ks * 16 + tig * 2;
            qa[ks][0] = *reinterpret_cast<const unsigned*>(&qp[gid * DHc + c]);
            qa[ks][1] = *reinterpret_cast<const unsigned*>(&qp[(gid + 8) * DHc + c]);
            qa[ks][2] = *reinterpret_cast<const unsigned*>(&qp[gid * DHc + c + 8]);
            qa[ks][3] = *reinterpret_cast<const unsigned*>(&qp[(gid + 8) * DHc + c + 8]);
        }
    }

    float4 oacc[8];
    #pragma unroll
    for (int i = 0; i < 8; i++) oacc[i] = make_float4(0.f, 0.f, 0.f, 0.f);
    float m0 = -1e30f, m1 = -1e30f, l0 = 0.f, l1 = 0.f;

    for (int kb = 0; kb < Nc; kb += 64) {
        __syncthreads();
        #pragma unroll
        for (int j = 0; j < 4; j++) {
            int fid = tid + 128 * j;
            int r = fid >> 3, c8 = (fid & 7) * 8;
            *reinterpret_cast<uint4*>(&Ks[r][c8]) =
                *reinterpret_cast<const uint4*>(&K[(kb + r) * DHc + c8]);
            *reinterpret_cast<uint4*>(&Vs[r][c8]) =
                *reinterpret_cast<const uint4*>(&V[(kb + r) * DHc + c8]);
        }
        __syncthreads();

        // S = Q K^T (16x64 per warp)
        float4 s[8];
        #pragma unroll
        for (int i = 0; i < 8; i++) s[i] = make_float4(0.f, 0.f, 0.f, 0.f);
        #pragma unroll
        for (int p = 0; p < 4; p++) {
            #pragma unroll
            for (int ks = 0; ks < 4; ks++) {
                unsigned b0, b1, b2, b3;
                ldsm4(b0, b1, b2, b3,
                      &Ks[p * 16 + (lane & 7) + 8 * (lane >> 4)]
                         [ks * 16 + 8 * ((lane >> 3) & 1)]);
                mma16(s[2 * p], qa[ks][0], qa[ks][1], qa[ks][2], qa[ks][3], b0, b1);
                mma16(s[2 * p + 1], qa[ks][0], qa[ks][1], qa[ks][2], qa[ks][3], b2, b3);
            }
        }

        // online softmax (rows gid, gid+8; row team = quad)
        float tm0 = -1e30f, tm1 = -1e30f;
        #pragma unroll
        for (int nt = 0; nt < 8; nt++) {
            s[nt].x *= 0.125f; s[nt].y *= 0.125f;
            s[nt].z *= 0.125f; s[nt].w *= 0.125f;
            tm0 = fmaxf(tm0, fmaxf(s[nt].x, s[nt].y));
            tm1 = fmaxf(tm1, fmaxf(s[nt].z, s[nt].w));
        }
        tm0 = fmaxf(tm0, __shfl_xor_sync(0xffffffffu, tm0, 1));
        tm0 = fmaxf(tm0, __shfl_xor_sync(0xffffffffu, tm0, 2));
        tm1 = fmaxf(tm1, __shfl_xor_sync(0xffffffffu, tm1, 1));
        tm1 = fmaxf(tm1, __shfl_xor_sync(0xffffffffu, tm1, 2));
        float nm0 = fmaxf(m0, tm0), nm1 = fmaxf(m1, tm1);
        float f0 = __expf(m0 - nm0), f1 = __expf(m1 - nm1);
        m0 = nm0; m1 = nm1;
        float ps0 = 0.f, ps1 = 0.f;
        #pragma unroll
        for (int nt = 0; nt < 8; nt++) {
            s[nt].x = __expf(s[nt].x - nm0);
            s[nt].y = __expf(s[nt].y - nm0);
            s[nt].z = __expf(s[nt].z - nm1);
            s[nt].w = __expf(s[nt].w - nm1);
            ps0 += s[nt].x + s[nt].y;
            ps1 += s[nt].z + s[nt].w;
        }
        ps0 += __shfl_xor_sync(0xffffffffu, ps0, 1);
        ps0 += __shfl_xor_sync(0xffffffffu, ps0, 2);
        ps1 += __shfl_xor_sync(0xffffffffu, ps1, 1);
        ps1 += __shfl_xor_sync(0xffffffffu, ps1, 2);
        l0 = l0 * f0 + ps0;
        l1 = l1 * f1 + ps1;
        #pragma unroll
        for (int nt = 0; nt < 8; nt++) {
            oacc[nt].x *= f0; oacc[nt].y *= f0;
            oacc[nt].z *= f1; oacc[nt].w *= f1;
        }

        // P -> smem (own-warp region), re-fragment via ldmatrix
        #pragma unroll
        for (int nt = 0; nt < 8; nt++) {
            int col = nt * 8 + tig * 2;
            *reinterpret_cast<unsigned*>(&Ps[wr + gid][col]) = pack_bf(s[nt].x, s[nt].y);
            *reinterpret_cast<unsigned*>(&Ps[wr + gid + 8][col]) = pack_bf(s[nt].z, s[nt].w);
        }
        __syncwarp();

        unsigned pa[4][4];
        #pragma unroll
        for (int ks = 0; ks < 4; ks++)
            ldsm4(pa[ks][0], pa[ks][1], pa[ks][2], pa[ks][3],
                  &Ps[wr + (lane & 15)][ks * 16 + (lane >> 4) * 8]);

        // O += P V (16x64 per warp)
        #pragma unroll
        for (int p = 0; p < 4; p++) {
            #pragma unroll
            for (int ks = 0; ks < 4; ks++) {
                unsigned b0, b1, b2, b3;
                ldsm4t(b0, b1, b2, b3,
                       &Vs[ks * 16 + (lane & 7) + 8 * ((lane >> 3) & 1)]
                          [p * 16 + (lane >> 4) * 8]);
                mma16(oacc[2 * p], pa[ks][0], pa[ks][1], pa[ks][2], pa[ks][3], b0, b1);
                mma16(oacc[2 * p + 1], pa[ks][0], pa[ks][1], pa[ks][2], pa[ks][3], b2, b3);
            }
        }
    }

    float i0 = 1.f / l0, i1 = 1.f / l1;
    unsigned* Y = reinterpret_cast<unsigned*>(buf_yb);
    int r0 = b * Nc + qBase + wr + gid, r1 = r0 + 8;
    #pragma unroll
    for (int nt = 0; nt < 8; nt++) {
        int cw = 32 * h + 4 * nt + tig;   // bf162 word index within row
        Y[r0 * 128 + cw] = pack_bf(oacc[nt].x * i0, oacc[nt].y * i0);
        Y[r1 * 128 + cw] = pack_bf(oacc[nt].z * i1, oacc[nt].w * i1);
    }
}

// ---------------------------------------------------------------------------
// 4) out = x + sigmoid(gate_pre) * y_out
// ---------------------------------------------------------------------------
__global__ void final_kernel(const float* __restrict__ x,
                             float* __restrict__ out) {
    int i = blockIdx.x * blockDim.x + threadIdx.x;
    float z = buf_gt[i];
    float gate = 1.f / (1.f + __expf(-z));
    out[i] = x[i] + gate * buf_yo[i];
}

// ---------------------------------------------------------------------------
extern "C" void kernel_launch(void* const* d_in, const int* in_sizes, int n_in,
                              void* d_out, int out_size) {
    (void)in_sizes; (void)n_in; (void)out_size;
    const float* x      = (const float*)d_in[0];
    const float* freqs  = (const float*)d_in[1];
    const float* g      = (const float*)d_in[2];
    const float* w_qkv  = (const float*)d_in[3];
    const float* b_qkv  = (const float*)d_in[4];
    const float* w_out  = (const float*)d_in[5];
    const float* b_out  = (const float*)d_in[6];
    const float* w_gate = (const float*)d_in[7];
    const float* b_gate = (const float*)d_in[8];
    float* out = (float*)d_out;

    rmsnorm_kernel<<<Mc, Dc>>>(x, g);
    gemm_qkv_kernel<<<dim3(12, 128), 128>>>(w_qkv, b_qkv, freqs);
    attn_kernel<<<Bc * Hc * (Nc / 64), 128>>>();
    gemm_og_kernel<<<dim3(4, 128, 2), 128>>>(w_out, b_out, w_gate, b_gate);
    final_kernel<<<(Mc * Dc) / 256, 256>>>(x, out);
}

// round 4
// speedup vs baseline: 10.1293x; 1.1052x over previous
#include <cuda_runtime.h>
#include <cuda_bf16.h>
#include <math.h>

// Problem constants
#define Bc 4
#define Nc 2048
#define Dc 256
#define Hc 4
#define DHc 64
#define Mc (Bc * Nc)          // 8192 rows
#define EPSc 1e-8f
#define LDH 72                // smem row pitch in halves (144B: ldsm conflict-free)

// Scratch (device globals; no allocation allowed)
__device__ __nv_bfloat16 buf_hb[Mc * Dc];          // normalized h, bf16
__device__ __nv_bfloat16 buf_q[Bc * Hc * Nc * DHc];
__device__ __nv_bfloat16 buf_k[Bc * Hc * Nc * DHc];
__device__ __nv_bfloat16 buf_v[Bc * Hc * Nc * DHc];
__device__ __nv_bfloat16 buf_yb[Mc * Dc];          // attention out, bf16
__device__ __nv_bfloat16 wqkv_b[Dc * 3 * Dc];      // bf16 weights
__device__ __nv_bfloat16 wout_b[Dc * Dc];
__device__ __nv_bfloat16 wgate_b[Dc * Dc];

// ---------------------------------------------------------------------------
// helpers
// ---------------------------------------------------------------------------
__device__ __forceinline__ unsigned pack_bf(float x, float y) {
    __nv_bfloat162 h = __float22bfloat162_rn(make_float2(x, y));
    return *reinterpret_cast<unsigned*>(&h);
}
__device__ __forceinline__ void mma16(float4& d, unsigned a0, unsigned a1,
                                      unsigned a2, unsigned a3,
                                      unsigned b0, unsigned b1) {
    asm volatile(
        "mma.sync.aligned.m16n8k16.row.col.f32.bf16.bf16.f32 "
        "{%0,%1,%2,%3},{%4,%5,%6,%7},{%8,%9},{%0,%1,%2,%3};"
        : "+f"(d.x), "+f"(d.y), "+f"(d.z), "+f"(d.w)
        : "r"(a0), "r"(a1), "r"(a2), "r"(a3), "r"(b0), "r"(b1));
}
__device__ __forceinline__ void ldsm4(unsigned& r0, unsigned& r1, unsigned& r2,
                                      unsigned& r3, const void* p) {
    unsigned a = (unsigned)__cvta_generic_to_shared(p);
    asm volatile("ldmatrix.sync.aligned.m8n8.x4.shared.b16 {%0,%1,%2,%3},[%4];"
                 : "=r"(r0), "=r"(r1), "=r"(r2), "=r"(r3) : "r"(a));
}
__device__ __forceinline__ void ldsm4t(unsigned& r0, unsigned& r1, unsigned& r2,
                                       unsigned& r3, const void* p) {
    unsigned a = (unsigned)__cvta_generic_to_shared(p);
    asm volatile("ldmatrix.sync.aligned.m8n8.x4.trans.shared.b16 {%0,%1,%2,%3},[%4];"
                 : "=r"(r0), "=r"(r1), "=r"(r2), "=r"(r3) : "r"(a));
}
__device__ __forceinline__ void cpasync16(void* dst, const void* src) {
    unsigned d = (unsigned)__cvta_generic_to_shared(dst);
    asm volatile("cp.async.ca.shared.global [%0], [%1], 16;" :: "r"(d), "l"(src));
}
__device__ __forceinline__ void cp_commit() {
    asm volatile("cp.async.commit_group;" ::: "memory");
}
__device__ __forceinline__ void cp_wait_all() {
    asm volatile("cp.async.wait_group 0;" ::: "memory");
}

// ---------------------------------------------------------------------------
// 0) convert all weights to bf16 (once per launch; tiny)
// ---------------------------------------------------------------------------
__global__ void convw_kernel(const float* __restrict__ wq,
                             const float* __restrict__ wo,
                             const float* __restrict__ wg) {
    int i = blockIdx.x * blockDim.x + threadIdx.x;  // float4 index < 81920
    const float* src;
    __nv_bfloat16* dst;
    int off;
    if (i < 49152)      { src = wq; dst = wqkv_b;  off = i; }
    else if (i < 65536) { src = wo; dst = wout_b;  off = i - 49152; }
    else                { src = wg; dst = wgate_b; off = i - 65536; }
    float4 v = reinterpret_cast<const float4*>(src)[off];
    *reinterpret_cast<uint2*>(dst + off * 4) =
        make_uint2(pack_bf(v.x, v.y), pack_bf(v.z, v.w));
}

// ---------------------------------------------------------------------------
// 1) zero-centered RMSNorm -> bf16 h
// ---------------------------------------------------------------------------
__global__ void rmsnorm_kernel(const float* __restrict__ x,
                               const float* __restrict__ g) {
    int row = blockIdx.x;
    int t = threadIdx.x;
    float v = x[row * Dc + t];
    __shared__ float red[8];
    float s = v;
    #pragma unroll
    for (int o = 16; o; o >>= 1) s += __shfl_xor_sync(0xffffffffu, s, o);
    if ((t & 31) == 0) red[t >> 5] = s;
    __syncthreads();
    float tot = 0.f;
    #pragma unroll
    for (int i = 0; i < 8; i++) tot += red[i];
    float mean = tot * (1.f / Dc);
    float x0 = v - mean;
    float s2 = x0 * x0;
    #pragma unroll
    for (int o = 16; o; o >>= 1) s2 += __shfl_xor_sync(0xffffffffu, s2, o);
    __syncthreads();
    if ((t & 31) == 0) red[t >> 5] = s2;
    __syncthreads();
    float tot2 = 0.f;
    #pragma unroll
    for (int i = 0; i < 8; i++) tot2 += red[i];
    float rinv = rsqrtf(tot2 * (1.f / Dc) + EPSc);
    buf_hb[row * Dc + t] = __float2bfloat16(x0 * rinv * g[t]);
}

// ---------------------------------------------------------------------------
// 2) pipelined bf16 mma GEMM mainloop (cp.async 2-stage)
//    acc[8] = A[64 rows, 256] @ W[256, 64 cols]; A,W bf16 row-major.
// ---------------------------------------------------------------------------
template <int NOUT>
__device__ __forceinline__ void gemm_main(
    const __nv_bfloat16* __restrict__ A, const __nv_bfloat16* __restrict__ W,
    __nv_bfloat16 (&As)[2][64][LDH], __nv_bfloat16 (&Ws)[2][64][LDH],
    float4 acc[8], int rowBase, int colBase) {
    int tid = threadIdx.x;
    int wid = tid >> 5, lane = tid & 31;
    int wr = wid * 16;
    #pragma unroll
    for (int i = 0; i < 8; i++) acc[i] = make_float4(0.f, 0.f, 0.f, 0.f);

    int lr = tid >> 3, lc8 = (tid & 7) * 8;   // loader: 128 thr x 4 = 512 chunks

    auto load_tile = [&](int s, int k0) {
        #pragma unroll
        for (int j = 0; j < 4; j++) {
            int r = lr + 16 * j;
            cpasync16(&As[s][r][lc8], &A[(rowBase + r) * Dc + k0 + lc8]);
            cpasync16(&Ws[s][r][lc8], &W[(k0 + r) * NOUT + colBase + lc8]);
        }
    };

    load_tile(0, 0);
    cp_commit();

    #pragma unroll
    for (int kc = 0; kc < 4; kc++) {
        cp_wait_all();
        __syncthreads();
        if (kc < 3) {
            load_tile((kc + 1) & 1, (kc + 1) * 64);
            cp_commit();
        }
        int s = kc & 1;
        #pragma unroll
        for (int ks = 0; ks < 4; ks++) {
            unsigned a0, a1, a2, a3;
            ldsm4(a0, a1, a2, a3, &As[s][wr + (lane & 15)][ks * 16 + (lane >> 4) * 8]);
            #pragma unroll
            for (int p = 0; p < 4; p++) {
                unsigned b0, b1, b2, b3;
                ldsm4t(b0, b1, b2, b3,
                       &Ws[s][ks * 16 + (lane & 7) + 8 * ((lane >> 3) & 1)]
                            [p * 16 + (lane >> 4) * 8]);
                mma16(acc[2 * p], a0, a1, a2, a3, b0, b1);
                mma16(acc[2 * p + 1], a0, a1, a2, a3, b2, b3);
            }
        }
        __syncthreads();
    }
}

// QKV GEMM with fused bias + RoPE + head scatter (bf16 outputs)
__global__ __launch_bounds__(128) void gemm_qkv_kernel(
    const float* __restrict__ bias, const float* __restrict__ freqs) {
    __shared__ __align__(16) __nv_bfloat16 As[2][64][LDH];
    __shared__ __align__(16) __nv_bfloat16 Ws[2][64][LDH];
    int rowBase = blockIdx.y * 64;
    int colBase = blockIdx.x * 64;
    float4 acc[8];
    gemm_main<3 * Dc>(buf_hb, wqkv_b, As, Ws, acc, rowBase, colBase);

    int tid = threadIdx.x;
    int wid = tid >> 5, lane = tid & 31;
    int gid = lane >> 2, tig = lane & 3;
    int sec = colBase >> 8;  // 0=q 1=k 2=v (uniform per block)
    unsigned* dst = sec == 0 ? reinterpret_cast<unsigned*>(buf_q)
                  : sec == 1 ? reinterpret_cast<unsigned*>(buf_k)
                             : reinterpret_cast<unsigned*>(buf_v);
    int r0 = rowBase + wid * 16 + gid, r1 = r0 + 8;
    int n0 = r0 & (Nc - 1), n1 = r1 & (Nc - 1);
    int b0i = r0 >> 11, b1i = r1 >> 11;
    #pragma unroll
    for (int nt = 0; nt < 8; nt++) {
        int col = colBase + nt * 8 + tig * 2;
        int c = col & 255, h = c >> 6, i = (c & 63) >> 1;
        float bx = bias[col], by = bias[col + 1];
        float v0 = acc[nt].x + bx, v1 = acc[nt].y + by;
        float w0 = acc[nt].z + bx, w1 = acc[nt].w + by;
        if (sec < 2) {
            float2 cs0 = *reinterpret_cast<const float2*>(&freqs[n0 * 64 + i * 2]);
            float2 cs1 = *reinterpret_cast<const float2*>(&freqs[n1 * 64 + i * 2]);
            float t0 = v0 * cs0.x - v1 * cs0.y;
            v1 = v0 * cs0.y + v1 * cs0.x; v0 = t0;
            float t1 = w0 * cs1.x - w1 * cs1.y;
            w1 = w0 * cs1.y + w1 * cs1.x; w0 = t1;
        }
        dst[((b0i * Hc + h) * Nc + n0) * 32 + i] = pack_bf(v0, v1);
        dst[((b1i * Hc + h) * Nc + n1) * 32 + i] = pack_bf(w0, w1);
    }
}

// Fused out-proj + gate + residual/gating epilogue
__global__ __launch_bounds__(128) void og_final_kernel(
    const float* __restrict__ bo, const float* __restrict__ bg,
    const float* __restrict__ x, float* __restrict__ out) {
    __shared__ __align__(16) __nv_bfloat16 As[2][64][LDH];
    __shared__ __align__(16) __nv_bfloat16 Ws[2][64][LDH];
    int rowBase = blockIdx.y * 64;
    int colBase = blockIdx.x * 64;
    float4 ao[8], ag[8];
    gemm_main<Dc>(buf_yb, wout_b, As, Ws, ao, rowBase, colBase);
    gemm_main<Dc>(buf_hb, wgate_b, As, Ws, ag, rowBase, colBase);

    int tid = threadIdx.x;
    int wid = tid >> 5, lane = tid & 31;
    int gid = lane >> 2, tig = lane & 3;
    int r0 = rowBase + wid * 16 + gid, r1 = r0 + 8;
    #pragma unroll
    for (int nt = 0; nt < 8; nt++) {
        int col = colBase + nt * 8 + tig * 2;
        float box = bo[col], boy = bo[col + 1];
        float bgx = bg[col], bgy = bg[col + 1];
        float g00 = 1.f / (1.f + __expf(-(ag[nt].x + bgx)));
        float g01 = 1.f / (1.f + __expf(-(ag[nt].y + bgy)));
        float g10 = 1.f / (1.f + __expf(-(ag[nt].z + bgx)));
        float g11 = 1.f / (1.f + __expf(-(ag[nt].w + bgy)));
        float2 x0 = *reinterpret_cast<const float2*>(&x[r0 * Dc + col]);
        float2 x1 = *reinterpret_cast<const float2*>(&x[r1 * Dc + col]);
        *reinterpret_cast<float2*>(&out[r0 * Dc + col]) =
            make_float2(x0.x + g00 * (ao[nt].x + box),
                        x0.y + g01 * (ao[nt].y + boy));
        *reinterpret_cast<float2*>(&out[r1 * Dc + col]) =
            make_float2(x1.x + g10 * (ao[nt].z + box),
                        x1.y + g11 * (ao[nt].w + boy));
    }
}

// ---------------------------------------------------------------------------
// 3) Flash attention, bf16 mma + ldmatrix + cp.async 2-stage K/V pipeline.
//    64 q-rows/block (4 warps x 16), K/V tiles of 64, online softmax.
// ---------------------------------------------------------------------------
__global__ __launch_bounds__(128) void attn_kernel() {
    __shared__ __align__(16) __nv_bfloat16 Ks[2][64][LDH];
    __shared__ __align__(16) __nv_bfloat16 Vs[2][64][LDH];
    __shared__ __align__(16) __nv_bfloat16 Ps[64][LDH];

    int tid = threadIdx.x;
    int wid = tid >> 5, lane = tid & 31;
    int gid = lane >> 2, tig = lane & 3;
    int bh = blockIdx.x >> 5;
    int qt = blockIdx.x & 31;
    int qBase = qt * 64;
    int b = bh >> 2, h = bh & 3;
    const __nv_bfloat16* Q = buf_q + bh * Nc * DHc;
    const __nv_bfloat16* K = buf_k + bh * Nc * DHc;
    const __nv_bfloat16* V = buf_v + bh * Nc * DHc;
    int wr = wid * 16;

    int lr = tid >> 3, lc8 = (tid & 7) * 8;
    auto load_kv = [&](int s, int kb) {
        #pragma unroll
        for (int j = 0; j < 4; j++) {
            int r = lr + 16 * j;
            cpasync16(&Ks[s][r][lc8], &K[(kb + r) * DHc + lc8]);
            cpasync16(&Vs[s][r][lc8], &V[(kb + r) * DHc + lc8]);
        }
    };

    load_kv(0, 0);
    cp_commit();

    // Q A-fragments straight from global (pairs are 32-bit words)
    unsigned qa[4][4];
    {
        const __nv_bfloat16* qp = Q + (qBase + wr) * DHc;
        #pragma unroll
        for (int ks = 0; ks < 4; ks++) {
            int c = ks * 16 + tig * 2;
            qa[ks][0] = *reinterpret_cast<const unsigned*>(&qp[gid * DHc + c]);
            qa[ks][1] = *reinterpret_cast<const unsigned*>(&qp[(gid + 8) * DHc + c]);
            qa[ks][2] = *reinterpret_cast<const unsigned*>(&qp[gid * DHc + c + 8]);
            qa[ks][3] = *reinterpret_cast<const unsigned*>(&qp[(gid + 8) * DHc + c + 8]);
        }
    }

    float4 oacc[8];
    #pragma unroll
    for (int i = 0; i < 8; i++) oacc[i] = make_float4(0.f, 0.f, 0.f, 0.f);
    float m0 = -1e30f, m1 = -1e30f, l0 = 0.f, l1 = 0.f;

    for (int t = 0; t < 32; t++) {
        cp_wait_all();
        __syncthreads();
        if (t < 31) {
            load_kv((t + 1) & 1, (t + 1) * 64);
            cp_commit();
        }
        int s = t & 1;

        // S = Q K^T (16x64 per warp)
        float4 sc[8];
        #pragma unroll
        for (int i = 0; i < 8; i++) sc[i] = make_float4(0.f, 0.f, 0.f, 0.f);
        #pragma unroll
        for (int p = 0; p < 4; p++) {
            #pragma unroll
            for (int ks = 0; ks < 4; ks++) {
                unsigned b0, b1, b2, b3;
                ldsm4(b0, b1, b2, b3,
                      &Ks[s][p * 16 + (lane & 7) + 8 * (lane >> 4)]
                           [ks * 16 + 8 * ((lane >> 3) & 1)]);
                mma16(sc[2 * p], qa[ks][0], qa[ks][1], qa[ks][2], qa[ks][3], b0, b1);
                mma16(sc[2 * p + 1], qa[ks][0], qa[ks][1], qa[ks][2], qa[ks][3], b2, b3);
            }
        }

        // online softmax (rows gid, gid+8; row team = quad)
        float tm0 = -1e30f, tm1 = -1e30f;
        #pragma unroll
        for (int nt = 0; nt < 8; nt++) {
            sc[nt].x *= 0.125f; sc[nt].y *= 0.125f;
            sc[nt].z *= 0.125f; sc[nt].w *= 0.125f;
            tm0 = fmaxf(tm0, fmaxf(sc[nt].x, sc[nt].y));
            tm1 = fmaxf(tm1, fmaxf(sc[nt].z, sc[nt].w));
        }
        tm0 = fmaxf(tm0, __shfl_xor_sync(0xffffffffu, tm0, 1));
        tm0 = fmaxf(tm0, __shfl_xor_sync(0xffffffffu, tm0, 2));
        tm1 = fmaxf(tm1, __shfl_xor_sync(0xffffffffu, tm1, 1));
        tm1 = fmaxf(tm1, __shfl_xor_sync(0xffffffffu, tm1, 2));
        float nm0 = fmaxf(m0, tm0), nm1 = fmaxf(m1, tm1);
        float f0 = __expf(m0 - nm0), f1 = __expf(m1 - nm1);
        m0 = nm0; m1 = nm1;
        float ps0 = 0.f, ps1 = 0.f;
        #pragma unroll
        for (int nt = 0; nt < 8; nt++) {
            sc[nt].x = __expf(sc[nt].x - nm0);
            sc[nt].y = __expf(sc[nt].y - nm0);
            sc[nt].z = __expf(sc[nt].z - nm1);
            sc[nt].w = __expf(sc[nt].w - nm1);
            ps0 += sc[nt].x + sc[nt].y;
            ps1 += sc[nt].z + sc[nt].w;
        }
        ps0 += __shfl_xor_sync(0xffffffffu, ps0, 1);
        ps0 += __shfl_xor_sync(0xffffffffu, ps0, 2);
        ps1 += __shfl_xor_sync(0xffffffffu, ps1, 1);
        ps1 += __shfl_xor_sync(0xffffffffu, ps1, 2);
        l0 = l0 * f0 + ps0;
        l1 = l1 * f1 + ps1;
        #pragma unroll
        for (int nt = 0; nt < 8; nt++) {
            oacc[nt].x *= f0; oacc[nt].y *= f0;
            oacc[nt].z *= f1; oacc[nt].w *= f1;
        }

        // P -> smem (own-warp region), re-fragment via ldmatrix
        #pragma unroll
        for (int nt = 0; nt < 8; nt++) {
            int col = nt * 8 + tig * 2;
            *reinterpret_cast<unsigned*>(&Ps[wr + gid][col]) = pack_bf(sc[nt].x, sc[nt].y);
            *reinterpret_cast<unsigned*>(&Ps[wr + gid + 8][col]) = pack_bf(sc[nt].z, sc[nt].w);
        }
        __syncwarp();

        unsigned pa[4][4];
        #pragma unroll
        for (int ks = 0; ks < 4; ks++)
            ldsm4(pa[ks][0], pa[ks][1], pa[ks][2], pa[ks][3],
                  &Ps[wr + (lane & 15)][ks * 16 + (lane >> 4) * 8]);

        // O += P V (16x64 per warp)
        #pragma unroll
        for (int p = 0; p < 4; p++) {
            #pragma unroll
            for (int ks = 0; ks < 4; ks++) {
                unsigned b0, b1, b2, b3;
                ldsm4t(b0, b1, b2, b3,
                       &Vs[s][ks * 16 + (lane & 7) + 8 * ((lane >> 3) & 1)]
                            [p * 16 + (lane >> 4) * 8]);
                mma16(oacc[2 * p], pa[ks][0], pa[ks][1], pa[ks][2], pa[ks][3], b0, b1);
                mma16(oacc[2 * p + 1], pa[ks][0], pa[ks][1], pa[ks][2], pa[ks][3], b2, b3);
            }
        }
        __syncthreads();
    }

    float i0 = 1.f / l0, i1 = 1.f / l1;
    unsigned* Y = reinterpret_cast<unsigned*>(buf_yb);
    int r0 = b * Nc + qBase + wr + gid, r1 = r0 + 8;
    #pragma unroll
    for (int nt = 0; nt < 8; nt++) {
        int cw = 32 * h + 4 * nt + tig;   // bf162 word index within row
        Y[r0 * 128 + cw] = pack_bf(oacc[nt].x * i0, oacc[nt].y * i0);
        Y[r1 * 128 + cw] = pack_bf(oacc[nt].z * i1, oacc[nt].w * i1);
    }
}

// ---------------------------------------------------------------------------
extern "C" void kernel_launch(void* const* d_in, const int* in_sizes, int n_in,
                              void* d_out, int out_size) {
    (void)in_sizes; (void)n_in; (void)out_size;
    const float* x      = (const float*)d_in[0];
    const float* freqs  = (const float*)d_in[1];
    const float* g      = (const float*)d_in[2];
    const float* w_qkv  = (const float*)d_in[3];
    const float* b_qkv  = (const float*)d_in[4];
    const float* w_out  = (const float*)d_in[5];
    const float* b_out  = (const float*)d_in[6];
    const float* w_gate = (const float*)d_in[7];
    const float* b_gate = (const float*)d_in[8];
    float* out = (float*)d_out;

    convw_kernel<<<320, 256>>>(w_qkv, w_out, w_gate);
    rmsnorm_kernel<<<Mc, Dc>>>(x, g);
    gemm_qkv_kernel<<<dim3(12, 128), 128>>>(b_qkv, freqs);
    attn_kernel<<<Bc * Hc * (Nc / 64), 128>>>();
    og_final_kernel<<<dim3(4, 128), 128>>>(b_out, b_gate, x, out);
}

// round 5
// speedup vs baseline: 12.0338x; 1.1880x over previous
#include <cuda_runtime.h>
#include <cuda_bf16.h>
#include <math.h>

// Problem constants
#define Bc 4
#define Nc 2048
#define Dc 256
#define Hc 4
#define DHc 64
#define Mc (Bc * Nc)          // 8192 rows
#define EPSc 1e-8f
#define LDH 72                // smem row pitch in halves (144B: ldsm conflict-free)
#define QSCALE 0.1803368801111204f   // 0.125 * log2(e)

// Scratch (device globals; no allocation allowed)
__device__ __nv_bfloat16 buf_hb[Mc * Dc];          // normalized h, bf16
__device__ __nv_bfloat16 buf_q[Bc * Hc * Nc * DHc]; // pre-scaled by QSCALE
__device__ __nv_bfloat16 buf_k[Bc * Hc * Nc * DHc];
__device__ __nv_bfloat16 buf_v[Bc * Hc * Nc * DHc];
__device__ __nv_bfloat16 buf_yb[Mc * Dc];          // attention out, bf16
__device__ __nv_bfloat16 wqkv_b[Dc * 3 * Dc];      // bf16 weights
__device__ __nv_bfloat16 wout_b[Dc * Dc];
__device__ __nv_bfloat16 wgate_b[Dc * Dc];

// ---------------------------------------------------------------------------
// helpers
// ---------------------------------------------------------------------------
__device__ __forceinline__ unsigned pack_bf(float x, float y) {
    __nv_bfloat162 h = __float22bfloat162_rn(make_float2(x, y));
    return *reinterpret_cast<unsigned*>(&h);
}
__device__ __forceinline__ void mma16(float4& d, unsigned a0, unsigned a1,
                                      unsigned a2, unsigned a3,
                                      unsigned b0, unsigned b1) {
    asm volatile(
        "mma.sync.aligned.m16n8k16.row.col.f32.bf16.bf16.f32 "
        "{%0,%1,%2,%3},{%4,%5,%6,%7},{%8,%9},{%0,%1,%2,%3};"
        : "+f"(d.x), "+f"(d.y), "+f"(d.z), "+f"(d.w)
        : "r"(a0), "r"(a1), "r"(a2), "r"(a3), "r"(b0), "r"(b1));
}
__device__ __forceinline__ void ldsm4(unsigned& r0, unsigned& r1, unsigned& r2,
                                      unsigned& r3, const void* p) {
    unsigned a = (unsigned)__cvta_generic_to_shared(p);
    asm volatile("ldmatrix.sync.aligned.m8n8.x4.shared.b16 {%0,%1,%2,%3},[%4];"
                 : "=r"(r0), "=r"(r1), "=r"(r2), "=r"(r3) : "r"(a));
}
__device__ __forceinline__ void ldsm4t(unsigned& r0, unsigned& r1, unsigned& r2,
                                       unsigned& r3, const void* p) {
    unsigned a = (unsigned)__cvta_generic_to_shared(p);
    asm volatile("ldmatrix.sync.aligned.m8n8.x4.trans.shared.b16 {%0,%1,%2,%3},[%4];"
                 : "=r"(r0), "=r"(r1), "=r"(r2), "=r"(r3) : "r"(a));
}
__device__ __forceinline__ void cpasync16(void* dst, const void* src) {
    unsigned d = (unsigned)__cvta_generic_to_shared(dst);
    asm volatile("cp.async.ca.shared.global [%0], [%1], 16;" :: "r"(d), "l"(src));
}
__device__ __forceinline__ void cp_commit() {
    asm volatile("cp.async.commit_group;" ::: "memory");
}
__device__ __forceinline__ void cp_wait_all() {
    asm volatile("cp.async.wait_group 0;" ::: "memory");
}

// ---------------------------------------------------------------------------
// 0) convert all weights to bf16 (once per launch; tiny)
// ---------------------------------------------------------------------------
__global__ void convw_kernel(const float* __restrict__ wq,
                             const float* __restrict__ wo,
                             const float* __restrict__ wg) {
    int i = blockIdx.x * blockDim.x + threadIdx.x;  // float4 index < 81920
    const float* src;
    __nv_bfloat16* dst;
    int off;
    if (i < 49152)      { src = wq; dst = wqkv_b;  off = i; }
    else if (i < 65536) { src = wo; dst = wout_b;  off = i - 49152; }
    else                { src = wg; dst = wgate_b; off = i - 65536; }
    float4 v = reinterpret_cast<const float4*>(src)[off];
    *reinterpret_cast<uint2*>(dst + off * 4) =
        make_uint2(pack_bf(v.x, v.y), pack_bf(v.z, v.w));
}

// ---------------------------------------------------------------------------
// 1) zero-centered RMSNorm -> bf16 h
// ---------------------------------------------------------------------------
__global__ void rmsnorm_kernel(const float* __restrict__ x,
                               const float* __restrict__ g) {
    int row = blockIdx.x;
    int t = threadIdx.x;
    float v = x[row * Dc + t];
    __shared__ float red[8];
    float s = v;
    #pragma unroll
    for (int o = 16; o; o >>= 1) s += __shfl_xor_sync(0xffffffffu, s, o);
    if ((t & 31) == 0) red[t >> 5] = s;
    __syncthreads();
    float tot = 0.f;
    #pragma unroll
    for (int i = 0; i < 8; i++) tot += red[i];
    float mean = tot * (1.f / Dc);
    float x0 = v - mean;
    float s2 = x0 * x0;
    #pragma unroll
    for (int o = 16; o; o >>= 1) s2 += __shfl_xor_sync(0xffffffffu, s2, o);
    __syncthreads();
    if ((t & 31) == 0) red[t >> 5] = s2;
    __syncthreads();
    float tot2 = 0.f;
    #pragma unroll
    for (int i = 0; i < 8; i++) tot2 += red[i];
    float rinv = rsqrtf(tot2 * (1.f / Dc) + EPSc);
    buf_hb[row * Dc + t] = __float2bfloat16(x0 * rinv * g[t]);
}

// ---------------------------------------------------------------------------
// 2) pipelined bf16 mma GEMM mainloop (cp.async 2-stage)
// ---------------------------------------------------------------------------
template <int NOUT>
__device__ __forceinline__ void gemm_main(
    const __nv_bfloat16* __restrict__ A, const __nv_bfloat16* __restrict__ W,
    __nv_bfloat16 (&As)[2][64][LDH], __nv_bfloat16 (&Ws)[2][64][LDH],
    float4 acc[8], int rowBase, int colBase) {
    int tid = threadIdx.x;
    int wid = tid >> 5, lane = tid & 31;
    int wr = wid * 16;
    #pragma unroll
    for (int i = 0; i < 8; i++) acc[i] = make_float4(0.f, 0.f, 0.f, 0.f);

    int lr = tid >> 3, lc8 = (tid & 7) * 8;

    auto load_tile = [&](int s, int k0) {
        #pragma unroll
        for (int j = 0; j < 4; j++) {
            int r = lr + 16 * j;
            cpasync16(&As[s][r][lc8], &A[(rowBase + r) * Dc + k0 + lc8]);
            cpasync16(&Ws[s][r][lc8], &W[(k0 + r) * NOUT + colBase + lc8]);
        }
    };

    load_tile(0, 0);
    cp_commit();

    #pragma unroll
    for (int kc = 0; kc < 4; kc++) {
        cp_wait_all();
        __syncthreads();
        if (kc < 3) {
            load_tile((kc + 1) & 1, (kc + 1) * 64);
            cp_commit();
        }
        int s = kc & 1;
        #pragma unroll
        for (int ks = 0; ks < 4; ks++) {
            unsigned a0, a1, a2, a3;
            ldsm4(a0, a1, a2, a3, &As[s][wr + (lane & 15)][ks * 16 + (lane >> 4) * 8]);
            #pragma unroll
            for (int p = 0; p < 4; p++) {
                unsigned b0, b1, b2, b3;
                ldsm4t(b0, b1, b2, b3,
                       &Ws[s][ks * 16 + (lane & 7) + 8 * ((lane >> 3) & 1)]
                            [p * 16 + (lane >> 4) * 8]);
                mma16(acc[2 * p], a0, a1, a2, a3, b0, b1);
                mma16(acc[2 * p + 1], a0, a1, a2, a3, b2, b3);
            }
        }
        __syncthreads();
    }
}

// QKV GEMM with fused bias + RoPE + head scatter (bf16 outputs; q pre-scaled)
__global__ __launch_bounds__(128) void gemm_qkv_kernel(
    const float* __restrict__ bias, const float* __restrict__ freqs) {
    __shared__ __align__(16) __nv_bfloat16 As[2][64][LDH];
    __shared__ __align__(16) __nv_bfloat16 Ws[2][64][LDH];
    int rowBase = blockIdx.y * 64;
    int colBase = blockIdx.x * 64;
    float4 acc[8];
    gemm_main<3 * Dc>(buf_hb, wqkv_b, As, Ws, acc, rowBase, colBase);

    int tid = threadIdx.x;
    int wid = tid >> 5, lane = tid & 31;
    int gid = lane >> 2, tig = lane & 3;
    int sec = colBase >> 8;  // 0=q 1=k 2=v (uniform per block)
    unsigned* dst = sec == 0 ? reinterpret_cast<unsigned*>(buf_q)
                  : sec == 1 ? reinterpret_cast<unsigned*>(buf_k)
                             : reinterpret_cast<unsigned*>(buf_v);
    float scl = sec == 0 ? QSCALE : 1.f;
    int r0 = rowBase + wid * 16 + gid, r1 = r0 + 8;
    int n0 = r0 & (Nc - 1), n1 = r1 & (Nc - 1);
    int b0i = r0 >> 11, b1i = r1 >> 11;
    #pragma unroll
    for (int nt = 0; nt < 8; nt++) {
        int col = colBase + nt * 8 + tig * 2;
        int c = col & 255, h = c >> 6, i = (c & 63) >> 1;
        float bx = bias[col], by = bias[col + 1];
        float v0 = acc[nt].x + bx, v1 = acc[nt].y + by;
        float w0 = acc[nt].z + bx, w1 = acc[nt].w + by;
        if (sec < 2) {
            float2 cs0 = *reinterpret_cast<const float2*>(&freqs[n0 * 64 + i * 2]);
            float2 cs1 = *reinterpret_cast<const float2*>(&freqs[n1 * 64 + i * 2]);
            float t0 = v0 * cs0.x - v1 * cs0.y;
            v1 = v0 * cs0.y + v1 * cs0.x; v0 = t0;
            float t1 = w0 * cs1.x - w1 * cs1.y;
            w1 = w0 * cs1.y + w1 * cs1.x; w0 = t1;
        }
        v0 *= scl; v1 *= scl; w0 *= scl; w1 *= scl;
        dst[((b0i * Hc + h) * Nc + n0) * 32 + i] = pack_bf(v0, v1);
        dst[((b1i * Hc + h) * Nc + n1) * 32 + i] = pack_bf(w0, w1);
    }
}

// Fused out-proj + gate + residual/gating epilogue
__global__ __launch_bounds__(128) void og_final_kernel(
    const float* __restrict__ bo, const float* __restrict__ bg,
    const float* __restrict__ x, float* __restrict__ out) {
    __shared__ __align__(16) __nv_bfloat16 As[2][64][LDH];
    __shared__ __align__(16) __nv_bfloat16 Ws[2][64][LDH];
    int rowBase = blockIdx.y * 64;
    int colBase = blockIdx.x * 64;
    float4 ao[8], ag[8];
    gemm_main<Dc>(buf_yb, wout_b, As, Ws, ao, rowBase, colBase);
    gemm_main<Dc>(buf_hb, wgate_b, As, Ws, ag, rowBase, colBase);

    int tid = threadIdx.x;
    int wid = tid >> 5, lane = tid & 31;
    int gid = lane >> 2, tig = lane & 3;
    int r0 = rowBase + wid * 16 + gid, r1 = r0 + 8;
    #pragma unroll
    for (int nt = 0; nt < 8; nt++) {
        int col = colBase + nt * 8 + tig * 2;
        float box = bo[col], boy = bo[col + 1];
        float bgx = bg[col], bgy = bg[col + 1];
        float g00 = 1.f / (1.f + __expf(-(ag[nt].x + bgx)));
        float g01 = 1.f / (1.f + __expf(-(ag[nt].y + bgy)));
        float g10 = 1.f / (1.f + __expf(-(ag[nt].z + bgx)));
        float g11 = 1.f / (1.f + __expf(-(ag[nt].w + bgy)));
        float2 x0 = *reinterpret_cast<const float2*>(&x[r0 * Dc + col]);
        float2 x1 = *reinterpret_cast<const float2*>(&x[r1 * Dc + col]);
        *reinterpret_cast<float2*>(&out[r0 * Dc + col]) =
            make_float2(x0.x + g00 * (ao[nt].x + box),
                        x0.y + g01 * (ao[nt].y + boy));
        *reinterpret_cast<float2*>(&out[r1 * Dc + col]) =
            make_float2(x1.x + g10 * (ao[nt].z + box),
                        x1.y + g11 * (ao[nt].w + boy));
    }
}

// ---------------------------------------------------------------------------
// 3) Flash attention. 128 q-rows/block, 4 warps x 32 rows (2 groups of 16).
//    K/V B-fragments reused across both q-groups (LDSM:MMA = 1:2).
//    P re-fragmentation is free (C-layout == A-layout). exp2-domain softmax.
// ---------------------------------------------------------------------------
__global__ __launch_bounds__(128) void attn_kernel() {
    __shared__ __align__(16) __nv_bfloat16 Ks[2][64][LDH];
    __shared__ __align__(16) __nv_bfloat16 Vs[2][64][LDH];

    int tid = threadIdx.x;
    int wid = tid >> 5, lane = tid & 31;
    int gid = lane >> 2, tig = lane & 3;
    int bh = blockIdx.x >> 4;     // 16 bh
    int qt = blockIdx.x & 15;     // 16 q tiles of 128
    int qBase = qt * 128;
    int b = bh >> 2, h = bh & 3;
    const __nv_bfloat16* Q = buf_q + bh * Nc * DHc;
    const __nv_bfloat16* K = buf_k + bh * Nc * DHc;
    const __nv_bfloat16* V = buf_v + bh * Nc * DHc;
    int wr = wid * 16;

    int lr = tid >> 3, lc8 = (tid & 7) * 8;
    auto load_kv = [&](int s, int kb) {
        #pragma unroll
        for (int j = 0; j < 4; j++) {
            int r = lr + 16 * j;
            cpasync16(&Ks[s][r][lc8], &K[(kb + r) * DHc + lc8]);
            cpasync16(&Vs[s][r][lc8], &V[(kb + r) * DHc + lc8]);
        }
    };

    load_kv(0, 0);
    cp_commit();

    // Q A-fragments for both 16-row groups (already scaled by QSCALE)
    unsigned qa[2][4][4];
    #pragma unroll
    for (int g = 0; g < 2; g++) {
        const __nv_bfloat16* qp = Q + (qBase + g * 64 + wr) * DHc;
        #pragma unroll
        for (int ks = 0; ks < 4; ks++) {
            int c = ks * 16 + tig * 2;
            qa[g][ks][0] = *reinterpret_cast<const unsigned*>(&qp[gid * DHc + c]);
            qa[g][ks][1] = *reinterpret_cast<const unsigned*>(&qp[(gid + 8) * DHc + c]);
            qa[g][ks][2] = *reinterpret_cast<const unsigned*>(&qp[gid * DHc + c + 8]);
            qa[g][ks][3] = *reinterpret_cast<const unsigned*>(&qp[(gid + 8) * DHc + c + 8]);
        }
    }

    float4 oacc[2][8];
    #pragma unroll
    for (int g = 0; g < 2; g++)
        #pragma unroll
        for (int i = 0; i < 8; i++) oacc[g][i] = make_float4(0.f, 0.f, 0.f, 0.f);
    float mx[4] = {-1e30f, -1e30f, -1e30f, -1e30f};
    float li[4] = {0.f, 0.f, 0.f, 0.f};

    for (int t = 0; t < 32; t++) {
        cp_wait_all();
        __syncthreads();
        if (t < 31) {
            load_kv((t + 1) & 1, (t + 1) * 64);
            cp_commit();
        }
        int s = t & 1;

        // S = Q K^T for both groups (K b-frags loaded once)
        float4 sc[2][8];
        #pragma unroll
        for (int g = 0; g < 2; g++)
            #pragma unroll
            for (int i = 0; i < 8; i++) sc[g][i] = make_float4(0.f, 0.f, 0.f, 0.f);
        #pragma unroll
        for (int p = 0; p < 4; p++) {
            #pragma unroll
            for (int ks = 0; ks < 4; ks++) {
                unsigned b0, b1, b2, b3;
                ldsm4(b0, b1, b2, b3,
                      &Ks[s][p * 16 + (lane & 7) + 8 * (lane >> 4)]
                           [ks * 16 + 8 * ((lane >> 3) & 1)]);
                #pragma unroll
                for (int g = 0; g < 2; g++) {
                    mma16(sc[g][2 * p], qa[g][ks][0], qa[g][ks][1],
                          qa[g][ks][2], qa[g][ks][3], b0, b1);
                    mma16(sc[g][2 * p + 1], qa[g][ks][0], qa[g][ks][1],
                          qa[g][ks][2], qa[g][ks][3], b2, b3);
                }
            }
        }

        // online softmax per group (scores already in log2 domain)
        unsigned pa[2][4][4];
        #pragma unroll
        for (int g = 0; g < 2; g++) {
            float tm0 = -1e30f, tm1 = -1e30f;
            #pragma unroll
            for (int nt = 0; nt < 8; nt++) {
                tm0 = fmaxf(tm0, fmaxf(sc[g][nt].x, sc[g][nt].y));
                tm1 = fmaxf(tm1, fmaxf(sc[g][nt].z, sc[g][nt].w));
            }
            tm0 = fmaxf(tm0, __shfl_xor_sync(0xffffffffu, tm0, 1));
            tm0 = fmaxf(tm0, __shfl_xor_sync(0xffffffffu, tm0, 2));
            tm1 = fmaxf(tm1, __shfl_xor_sync(0xffffffffu, tm1, 1));
            tm1 = fmaxf(tm1, __shfl_xor_sync(0xffffffffu, tm1, 2));
            float nm0 = fmaxf(mx[2 * g], tm0), nm1 = fmaxf(mx[2 * g + 1], tm1);
            float f0 = exp2f(mx[2 * g] - nm0), f1 = exp2f(mx[2 * g + 1] - nm1);
            mx[2 * g] = nm0; mx[2 * g + 1] = nm1;
            float ps0 = 0.f, ps1 = 0.f;
            #pragma unroll
            for (int nt = 0; nt < 8; nt++) {
                sc[g][nt].x = exp2f(sc[g][nt].x - nm0);
                sc[g][nt].y = exp2f(sc[g][nt].y - nm0);
                sc[g][nt].z = exp2f(sc[g][nt].z - nm1);
                sc[g][nt].w = exp2f(sc[g][nt].w - nm1);
                ps0 += sc[g][nt].x + sc[g][nt].y;
                ps1 += sc[g][nt].z + sc[g][nt].w;
            }
            ps0 += __shfl_xor_sync(0xffffffffu, ps0, 1);
            ps0 += __shfl_xor_sync(0xffffffffu, ps0, 2);
            ps1 += __shfl_xor_sync(0xffffffffu, ps1, 1);
            ps1 += __shfl_xor_sync(0xffffffffu, ps1, 2);
            li[2 * g] = li[2 * g] * f0 + ps0;
            li[2 * g + 1] = li[2 * g + 1] * f1 + ps1;
            if (f0 != 1.f || f1 != 1.f) {
                #pragma unroll
                for (int nt = 0; nt < 8; nt++) {
                    oacc[g][nt].x *= f0; oacc[g][nt].y *= f0;
                    oacc[g][nt].z *= f1; oacc[g][nt].w *= f1;
                }
            }
            // P: C-layout == A-layout, pack in registers (no smem round trip)
            #pragma unroll
            for (int ks = 0; ks < 4; ks++) {
                pa[g][ks][0] = pack_bf(sc[g][2 * ks].x, sc[g][2 * ks].y);
                pa[g][ks][1] = pack_bf(sc[g][2 * ks].z, sc[g][2 * ks].w);
                pa[g][ks][2] = pack_bf(sc[g][2 * ks + 1].x, sc[g][2 * ks + 1].y);
                pa[g][ks][3] = pack_bf(sc[g][2 * ks + 1].z, sc[g][2 * ks + 1].w);
            }
        }

        // O += P V for both groups (V b-frags loaded once)
        #pragma unroll
        for (int p = 0; p < 4; p++) {
            #pragma unroll
            for (int ks = 0; ks < 4; ks++) {
                unsigned b0, b1, b2, b3;
                ldsm4t(b0, b1, b2, b3,
                       &Vs[s][ks * 16 + (lane & 7) + 8 * ((lane >> 3) & 1)]
                            [p * 16 + (lane >> 4) * 8]);
                #pragma unroll
                for (int g = 0; g < 2; g++) {
                    mma16(oacc[g][2 * p], pa[g][ks][0], pa[g][ks][1],
                          pa[g][ks][2], pa[g][ks][3], b0, b1);
                    mma16(oacc[g][2 * p + 1], pa[g][ks][0], pa[g][ks][1],
                          pa[g][ks][2], pa[g][ks][3], b2, b3);
                }
            }
        }
        __syncthreads();
    }

    unsigned* Y = reinterpret_cast<unsigned*>(buf_yb);
    #pragma unroll
    for (int g = 0; g < 2; g++) {
        float i0 = 1.f / li[2 * g], i1 = 1.f / li[2 * g + 1];
        int r0 = b * Nc + qBase + g * 64 + wr + gid, r1 = r0 + 8;
        #pragma unroll
        for (int nt = 0; nt < 8; nt++) {
            int cw = 32 * h + 4 * nt + tig;   // bf162 word index within row
            Y[r0 * 128 + cw] = pack_bf(oacc[g][nt].x * i0, oacc[g][nt].y * i0);
            Y[r1 * 128 + cw] = pack_bf(oacc[g][nt].z * i1, oacc[g][nt].w * i1);
        }
    }
}

// ---------------------------------------------------------------------------
extern "C" void kernel_launch(void* const* d_in, const int* in_sizes, int n_in,
                              void* d_out, int out_size) {
    (void)in_sizes; (void)n_in; (void)out_size;
    const float* x      = (const float*)d_in[0];
    const float* freqs  = (const float*)d_in[1];
    const float* g      = (const float*)d_in[2];
    const float* w_qkv  = (const float*)d_in[3];
    const float* b_qkv  = (const float*)d_in[4];
    const float* w_out  = (const float*)d_in[5];
    const float* b_out  = (const float*)d_in[6];
    const float* w_gate = (const float*)d_in[7];
    const float* b_gate = (const float*)d_in[8];
    float* out = (float*)d_out;

    convw_kernel<<<320, 256>>>(w_qkv, w_out, w_gate);
    rmsnorm_kernel<<<Mc, Dc>>>(x, g);
    gemm_qkv_kernel<<<dim3(12, 128), 128>>>(b_qkv, freqs);
    attn_kernel<<<Bc * Hc * (Nc / 128), 128>>>();
    og_final_kernel<<<dim3(4, 128), 128>>>(b_out, b_gate, x, out);
}